// round 9
// baseline (speedup 1.0000x reference)
#include <cuda_runtime.h>
#include <cuda_fp16.h>
#include <math.h>
#include <stdint.h>

// ---------------- problem constants ----------------
#define SEQ_LEN   65536
#define NN        256
#define NC        32
#define LW        16
#define NL        14
#define NF        200
#define ROWS      128      // M per CTA
#define NTHREADS  512      // 16 warps: 8 row-groups x 2 n-halves
#define AS        264      // A row stride in fp16 elems (528 B) -> conflict-free ldmatrix

// ---------------- smem map (bytes) ----------------
// B packed layout: r-row = (j*4 + tig), each row 40 u32 words; word[n*2+h] holds
// fp16 pair for parent-pair kk = j*8 + tig + 4*h, column n. LDS.64 -> both b frags.
#define OFF_ACTS  0
#define OFF_XS    1024
#define OFF_BP    2048
#define BROW      40                        // u32 words per r-row
#define BHALF     (64 * BROW * 4)           // 10240 B (hi or lo)
#define BBUF      (2 * BHALF)               // 20480 B
#define OFF_STAGE (OFF_BP + 3 * BBUF)       // 63488: 2 x 15360 raw fp32 W stage
#define STAGEB    15360
#define OFF_AHI   (OFF_STAGE + 2 * STAGEB)  // 94208
#define ABYTES    (ROWS * AS * 2)           // 67584
#define OFF_ALO   (OFF_AHI + ABYTES)
#define SMEM_BYTES (OFF_ALO + ABYTES)       // 229376

// ---------------- helpers ----------------
__device__ __forceinline__ uint32_t smem_u32(const void* p) {
    uint32_t a;
    asm("{ .reg .u64 t; cvta.to.shared.u64 t, %1; cvt.u32.u64 %0, t; }" : "=r"(a) : "l"(p));
    return a;
}
__device__ __forceinline__ void ldsm_x4(uint32_t a[4], uint32_t addr) {
    asm volatile("ldmatrix.sync.aligned.m8n8.x4.shared.b16 {%0,%1,%2,%3}, [%4];"
        : "=r"(a[0]), "=r"(a[1]), "=r"(a[2]), "=r"(a[3]) : "r"(addr));
}
__device__ __forceinline__ void mma16816(float c[4], const uint32_t a[4], uint32_t b0, uint32_t b1) {
    asm volatile("mma.sync.aligned.m16n8k16.row.col.f32.f16.f16.f32 "
        "{%0,%1,%2,%3}, {%4,%5,%6,%7}, {%8,%9}, {%0,%1,%2,%3};"
        : "+f"(c[0]), "+f"(c[1]), "+f"(c[2]), "+f"(c[3])
        : "r"(a[0]), "r"(a[1]), "r"(a[2]), "r"(a[3]), "r"(b0), "r"(b1));
}
__device__ __forceinline__ void split16(float v, uint16_t& h, uint16_t& l) {
    __half hh = __float2half_rn(v);
    float  r  = v - __half2float(hh);
    __half ll = __float2half_rn(r);
    h = __half_as_ushort(hh);
    l = __half_as_ushort(ll);
}
__device__ __forceinline__ float ex2a(float x) {
    float r; asm("ex2.approx.f32 %0, %1;" : "=f"(r) : "f"(x)); return r;
}
__device__ __forceinline__ float rcpa(float x) {
    float r; asm("rcp.approx.f32 %0, %1;" : "=f"(r) : "f"(x)); return r;
}
__device__ __forceinline__ float actf(int aid, float z) {
    if (aid == 0) return z;
    if (aid == 2) return fmaxf(z, 0.f);
    if (aid == 1) {                       // tanh(z) = 1 - 2/(1+e^{2z})
        float t = ex2a(z * 2.8853900817779268f);
        return fmaf(-2.f, rcpa(t + 1.f), 1.f);
    }
    float t = ex2a(-z * 1.4426950408889634f);      // sigmoid
    return rcpa(1.f + t);
}
__device__ __forceinline__ float readA(const char* hi, const char* lo, int m, int node) {
    uint32_t b = (uint32_t)m * (AS * 2) + (uint32_t)node * 2;
    return __half2float(*(const __half*)(hi + b)) + __half2float(*(const __half*)(lo + b));
}
// packed-B byte offset for parent p, col n (within hi or lo half)
__device__ __forceinline__ uint32_t bOff(int p, int n) {
    int kk = p >> 1, parity = p & 1;
    int r  = ((kk >> 3) << 2) + (kk & 3);
    int h  = (kk >> 2) & 1;
    return (uint32_t)((r * BROW + n * 2 + h) << 2) + (uint32_t)(parity << 1);
}
// issue cp.async for W[0:Pn, nb:nb+16] -> stage; chunk c handled by thread c%NTHREADS
__device__ __forceinline__ void issueW(const float* __restrict__ W, int nb,
                                       uint32_t stage, int Pn, int tid) {
    const int nchunks = Pn * 4;
    for (int c = tid; c < nchunks; c += NTHREADS) {
        int p = c >> 2, s = c & 3;
        const float* src = W + (size_t)p * NN + nb + s * 4;
        asm volatile("cp.async.cg.shared.global [%0], [%1], 16;"
            :: "r"(stage + (uint32_t)p * 64 + (uint32_t)s * 16), "l"(src) : "memory");
    }
}
// convert staged fp32 W -> packed hi/lo fp16; SAME chunk->thread map as issueW
__device__ __forceinline__ void convertW(const float* __restrict__ stg,
                                         char* bHi, char* bLo, int Pn, int tid) {
    const int nchunks = Pn * 4;
    for (int c = tid; c < nchunks; c += NTHREADS) {
        int p = c >> 2, s = c & 3;
        float4 v = *(const float4*)(stg + p * 16 + s * 4);
        float vv[4] = { v.x, v.y, v.z, v.w };
        #pragma unroll
        for (int i = 0; i < 4; ++i) {
            int n = s * 4 + i;
            uint16_t h, l; split16(vv[i], h, l);
            uint32_t byte = bOff(p, n);
            *(uint16_t*)(bHi + byte) = h;
            *(uint16_t*)(bLo + byte) = l;
        }
    }
}

__global__ __launch_bounds__(NTHREADS, 1)
void scm_kernel(const float* __restrict__ causes,
                const float* __restrict__ W,
                const float* __restrict__ eps,
                const int*   __restrict__ act_ids,
                const int*   __restrict__ x_idx,
                const int*   __restrict__ y_idx_p,
                float*       __restrict__ out)
{
    extern __shared__ char smem[];
    const uint32_t sb = smem_u32(smem);
    int*  acts = (int*)(smem + OFF_ACTS);
    int*  xs   = (int*)(smem + OFF_XS);
    char* Ahi  = smem + OFF_AHI;
    char* Alo  = smem + OFF_ALO;

    const int tid  = threadIdx.x;
    const int lane = tid & 31;
    const int g    = lane >> 2;
    const int tig  = lane & 3;
    const int wid  = tid >> 5;
    const int rg   = wid & 7;
    const int nh   = wid >> 3;
    const int R    = rg * 16;
    const int row0 = blockIdx.x * ROWS;

    if (tid < NN) acts[tid] = act_ids[tid];
    if (tid < NF) xs[tid]   = x_idx[tid];

    // ---- roots: A[:, 0:32] = hi/lo split of clip(causes, -5, 5) ----
    {
        int m = tid >> 2, q = tid & 3;
        const float4* c4 = (const float4*)(causes + (size_t)(row0 + m) * NC + q * 8);
        float4 a = c4[0], b = c4[1];
        float v[8] = { a.x,a.y,a.z,a.w, b.x,b.y,b.z,b.w };
        uint32_t whi[4], wlo[4];
        #pragma unroll
        for (int i = 0; i < 4; ++i) {
            uint16_t h0, l0, h1, l1;
            float v0 = fminf(fmaxf(v[2*i],   -5.f), 5.f);
            float v1 = fminf(fmaxf(v[2*i+1], -5.f), 5.f);
            split16(v0, h0, l0); split16(v1, h1, l1);
            whi[i] = (uint32_t)h0 | ((uint32_t)h1 << 16);
            wlo[i] = (uint32_t)l0 | ((uint32_t)l1 << 16);
        }
        uint32_t base = (uint32_t)m * (AS * 2) + (uint32_t)q * 16;
        *(uint4*)(Ahi + base) = make_uint4(whi[0], whi[1], whi[2], whi[3]);
        *(uint4*)(Alo + base) = make_uint4(wlo[0], wlo[1], wlo[2], wlo[3]);
    }

    // ---- pack B(0) directly; async-stage W(1) into stage slot 1 ----
    {
        char* bHi = smem + OFF_BP;          // buffer 0
        char* bLo = bHi + BHALF;
        for (int e = tid; e < NC * 16; e += NTHREADS) {
            int p = e >> 4, n = e & 15;
            uint16_t h, l; split16(W[(size_t)p * NN + NC + n], h, l);
            uint32_t byte = bOff(p, n);
            *(uint16_t*)(bHi + byte) = h;
            *(uint16_t*)(bLo + byte) = l;
        }
        issueW(W, NC + LW, sb + OFF_STAGE + STAGEB, NC + LW, tid);
        asm volatile("cp.async.commit_group;" ::: "memory");
    }
    __syncthreads();

    const uint32_t a_addr = sb + OFF_AHI
                          + (uint32_t)(R + (lane & 15)) * (AS * 2)
                          + (uint32_t)((lane >> 4) * 8) * 2;
    const int bcol = nh * 8 + g;
    const uint32_t bwoff = (uint32_t)(tig * BROW + bcol * 2) * 4;   // per-warp b-frag offset

    for (int k = 0; k < NL; ++k) {
        const int nb   = NC + k * LW;
        const int nch  = nb >> 4;
        const char* bp = smem + OFF_BP + (k % 3) * BBUF;

        // async stage of W(k+2) -> stage slot (k&1)
        if (k < NL - 2) {
            const int nb2 = NC + (k + 2) * LW;
            issueW(W, nb2, sb + OFF_STAGE + (k & 1) * STAGEB, nb2, tid);
        }
        asm volatile("cp.async.commit_group;" ::: "memory");

        // eps LDG early: consumed in the epilogue (post-sync), latency spans the layer
        const int col0 = nb + nh * 8 + 2 * tig;
        float2 ev0 = *(const float2*)(eps + (size_t)(row0 + R + g)     * NN + col0);
        float2 ev1 = *(const float2*)(eps + (size_t)(row0 + R + g + 8) * NN + col0);

        // 3 independent accumulator chains (hh / hl / lh), 16x8 tile
        float chh[4] = {0,0,0,0}, chl[4] = {0,0,0,0}, clh[4] = {0,0,0,0};

        // --- pre-sync: old chunks (columns published at earlier barriers) ---
        const int jlast = nch - 1;
        for (int j = 0; j < jlast; ++j) {
            uint32_t ahi[4], alo[4];
            ldsm_x4(ahi, a_addr + j * 32);
            ldsm_x4(alo, a_addr + ABYTES + j * 32);
            uint2 bh = *(const uint2*)(bp + (uint32_t)j * (4 * BROW * 4) + bwoff);
            uint2 bl = *(const uint2*)(bp + BHALF + (uint32_t)j * (4 * BROW * 4) + bwoff);
            mma16816(chh, ahi, bh.x, bh.y);
            mma16816(chl, ahi, bl.x, bl.y);
            mma16816(clh, alo, bh.x, bh.y);
        }

        // convert staged W(k+1) -> B((k+1)%3); self-issued chunks only
        if (k < NL - 1) {
            asm volatile("cp.async.wait_group 1;" ::: "memory");
            char* bHi = smem + OFF_BP + ((k + 1) % 3) * BBUF;
            convertW((const float*)(smem + OFF_STAGE + ((k + 1) & 1) * STAGEB),
                     bHi, bHi + BHALF, nb + LW, tid);
        }

        __syncthreads();   // publishes prev epilogue's A cols + B(k+1)

        // --- post-sync: newest chunk ---
        {
            const int j = jlast;
            uint32_t ahi[4], alo[4];
            ldsm_x4(ahi, a_addr + j * 32);
            ldsm_x4(alo, a_addr + ABYTES + j * 32);
            uint2 bh = *(const uint2*)(bp + (uint32_t)j * (4 * BROW * 4) + bwoff);
            uint2 bl = *(const uint2*)(bp + BHALF + (uint32_t)j * (4 * BROW * 4) + bwoff);
            mma16816(chh, ahi, bh.x, bh.y);
            mma16816(chl, ahi, bl.x, bl.y);
            mma16816(clh, alo, bh.x, bh.y);
        }

        // epilogue: z = C + eps, activation, hi/lo split, store back to A
        {
            const int aid0 = acts[col0], aid1 = acts[col0 + 1];
            float z0 = chh[0] + (chl[0] + clh[0]) + ev0.x;
            float z1 = chh[1] + (chl[1] + clh[1]) + ev0.y;
            float z2 = chh[2] + (chl[2] + clh[2]) + ev1.x;
            float z3 = chh[3] + (chl[3] + clh[3]) + ev1.y;
            float a0 = actf(aid0, z0), a1 = actf(aid1, z1);
            float a2 = actf(aid0, z2), a3 = actf(aid1, z3);
            uint16_t h0,l0,h1,l1,h2,l2,h3,l3;
            split16(a0,h0,l0); split16(a1,h1,l1); split16(a2,h2,l2); split16(a3,h3,l3);
            uint32_t b0 = (uint32_t)(R + g)     * (AS * 2) + (uint32_t)col0 * 2;
            uint32_t b1 = (uint32_t)(R + g + 8) * (AS * 2) + (uint32_t)col0 * 2;
            *(uint32_t*)(Ahi + b0) = (uint32_t)h0 | ((uint32_t)h1 << 16);
            *(uint32_t*)(Alo + b0) = (uint32_t)l0 | ((uint32_t)l1 << 16);
            *(uint32_t*)(Ahi + b1) = (uint32_t)h2 | ((uint32_t)h3 << 16);
            *(uint32_t*)(Alo + b1) = (uint32_t)l2 | ((uint32_t)l3 << 16);
        }
    }
    __syncthreads();   // publish final layer's A columns

    // ---- outputs ----
    const int yidx = y_idx_p ? *y_idx_p : (NN - 1);
    float* Xout = out;
    float* yout = out + (size_t)SEQ_LEN * NF;

    if (tid < ROWS) {
        float v = readA(Ahi, Alo, tid, yidx);
        if (v != v) v = 0.f;
        yout[row0 + tid] = v;
    }
    for (int idx = tid; idx < ROWS * NF; idx += NTHREADS) {
        int r = idx / NF, j = idx - r * NF;
        float v = readA(Ahi, Alo, r, xs[j]);
        if (v != v) v = 0.f;
        v = fminf(fmaxf(v, -15.f), 15.f);
        Xout[(size_t)(row0 + r) * NF + j] = v;
    }
}

extern "C" void kernel_launch(void* const* d_in, const int* in_sizes, int n_in,
                              void* d_out, int out_size)
{
    const float* causes  = (const float*)d_in[0];
    const float* W       = (const float*)d_in[1];
    const float* eps     = (const float*)d_in[2];
    const int*   act_ids = (const int*)d_in[3];
    const int*   x_idx   = (const int*)d_in[4];
    const int*   y_idx_p = (n_in > 5) ? (const int*)d_in[5] : nullptr;
    float*       out     = (float*)d_out;

    cudaFuncSetAttribute(scm_kernel, cudaFuncAttributeMaxDynamicSharedMemorySize, SMEM_BYTES);

    scm_kernel<<<SEQ_LEN / ROWS, NTHREADS, SMEM_BYTES>>>(
        causes, W, eps, act_ids, x_idx, y_idx_p, out);
    (void)in_sizes; (void)out_size;
}

// round 10
// speedup vs baseline: 1.0803x; 1.0803x over previous
#include <cuda_runtime.h>
#include <cuda_fp16.h>
#include <math.h>
#include <stdint.h>

// ---------------- problem constants ----------------
#define SEQ_LEN   65536
#define NN        256
#define NC        32
#define LW        16
#define NL        14
#define NF        200
#define ROWS      64       // M per CTA (2 CTAs/SM)
#define NTHREADS  256      // 8 warps: 4 row-groups x 2 n-halves
#define AS        264      // A row stride in fp16 elems (528 B) -> conflict-free ldmatrix

// ---------------- smem map (bytes) ----------------
// B packed layout: r-row = (j*4 + tig), each row 40 u32 words; word[n*2+h] holds
// fp16 pair for parent-pair kk = j*8 + tig + 4*h, column n. LDS.64 -> both b frags.
#define OFF_ACTS  0
#define OFF_XS    1024
#define OFF_BP    2048
#define BROW      40                        // u32 words per r-row
#define BHALF     (64 * BROW * 4)           // 10240 B (hi or lo)
#define BBUF      (2 * BHALF)               // 20480 B
#define OFF_AHI   (OFF_BP + 2 * BBUF)       // 43008
#define ABYTES    (ROWS * AS * 2)           // 33792
#define OFF_ALO   (OFF_AHI + ABYTES)        // 76800
#define SMEM_BYTES (OFF_ALO + ABYTES)       // 110592  -> 2 CTAs/SM

// ---------------- helpers ----------------
__device__ __forceinline__ uint32_t smem_u32(const void* p) {
    uint32_t a;
    asm("{ .reg .u64 t; cvta.to.shared.u64 t, %1; cvt.u32.u64 %0, t; }" : "=r"(a) : "l"(p));
    return a;
}
__device__ __forceinline__ void ldsm_x4(uint32_t a[4], uint32_t addr) {
    asm volatile("ldmatrix.sync.aligned.m8n8.x4.shared.b16 {%0,%1,%2,%3}, [%4];"
        : "=r"(a[0]), "=r"(a[1]), "=r"(a[2]), "=r"(a[3]) : "r"(addr));
}
__device__ __forceinline__ void mma16816(float c[4], const uint32_t a[4], uint32_t b0, uint32_t b1) {
    asm volatile("mma.sync.aligned.m16n8k16.row.col.f32.f16.f16.f32 "
        "{%0,%1,%2,%3}, {%4,%5,%6,%7}, {%8,%9}, {%0,%1,%2,%3};"
        : "+f"(c[0]), "+f"(c[1]), "+f"(c[2]), "+f"(c[3])
        : "r"(a[0]), "r"(a[1]), "r"(a[2]), "r"(a[3]), "r"(b0), "r"(b1));
}
__device__ __forceinline__ void split16(float v, uint16_t& h, uint16_t& l) {
    __half hh = __float2half_rn(v);
    float  r  = v - __half2float(hh);
    __half ll = __float2half_rn(r);
    h = __half_as_ushort(hh);
    l = __half_as_ushort(ll);
}
__device__ __forceinline__ float ex2a(float x) {
    float r; asm("ex2.approx.f32 %0, %1;" : "=f"(r) : "f"(x)); return r;
}
__device__ __forceinline__ float rcpa(float x) {
    float r; asm("rcp.approx.f32 %0, %1;" : "=f"(r) : "f"(x)); return r;
}
__device__ __forceinline__ float actf(int aid, float z) {
    if (aid == 0) return z;
    if (aid == 2) return fmaxf(z, 0.f);
    if (aid == 1) {                       // tanh(z) = 1 - 2/(1+e^{2z})
        float t = ex2a(z * 2.8853900817779268f);
        return fmaf(-2.f, rcpa(t + 1.f), 1.f);
    }
    float t = ex2a(-z * 1.4426950408889634f);      // sigmoid
    return rcpa(1.f + t);
}
__device__ __forceinline__ float readA(const char* hi, const char* lo, int m, int node) {
    uint32_t b = (uint32_t)m * (AS * 2) + (uint32_t)node * 2;
    return __half2float(*(const __half*)(hi + b)) + __half2float(*(const __half*)(lo + b));
}
// packed-B byte offset for parent p, col n (within hi or lo half)
__device__ __forceinline__ uint32_t bOff(int p, int n) {
    int kk = p >> 1, parity = p & 1;
    int r  = ((kk >> 3) << 2) + (kk & 3);
    int h  = (kk >> 2) & 1;
    return (uint32_t)((r * BROW + n * 2 + h) << 2) + (uint32_t)(parity << 1);
}

// B fragment: pair of uint2 (hi, lo)
struct BFrag { uint2 h, l; };
struct Frag  { uint32_t ahi[4], alo[4]; BFrag b; };

__device__ __forceinline__ void load_frag(Frag& f, uint32_t a_addr, const char* bp,
                                          uint32_t bwoff, int j) {
    ldsm_x4(f.ahi, a_addr + (uint32_t)j * 32);
    ldsm_x4(f.alo, a_addr + ABYTES + (uint32_t)j * 32);
    f.b.h = *(const uint2*)(bp + (uint32_t)j * (4 * BROW * 4) + bwoff);
    f.b.l = *(const uint2*)(bp + BHALF + (uint32_t)j * (4 * BROW * 4) + bwoff);
}
__device__ __forceinline__ void do_mmas(float chh[4], float chl[4], float clh[4], const Frag& f) {
    mma16816(chh, f.ahi, f.b.h.x, f.b.h.y);
    mma16816(chl, f.ahi, f.b.l.x, f.b.l.y);
    mma16816(clh, f.alo, f.b.h.x, f.b.h.y);
}

__global__ __launch_bounds__(NTHREADS, 2)
void scm_kernel(const float* __restrict__ causes,
                const float* __restrict__ W,
                const float* __restrict__ eps,
                const int*   __restrict__ act_ids,
                const int*   __restrict__ x_idx,
                const int*   __restrict__ y_idx_p,
                float*       __restrict__ out)
{
    extern __shared__ char smem[];
    const uint32_t sb = smem_u32(smem);
    int*  acts = (int*)(smem + OFF_ACTS);
    int*  xs   = (int*)(smem + OFF_XS);
    char* Ahi  = smem + OFF_AHI;
    char* Alo  = smem + OFF_ALO;

    const int tid  = threadIdx.x;
    const int lane = tid & 31;
    const int g    = lane >> 2;
    const int tig  = lane & 3;
    const int wid  = tid >> 5;
    const int rg   = wid & 3;          // row group 0..3
    const int nh   = wid >> 2;         // n-half 0/1
    const int R    = rg * 16;
    const int row0 = blockIdx.x * ROWS;

    if (tid < NN) acts[tid] = act_ids[tid];
    if (tid < NF) xs[tid]   = x_idx[tid];

    // ---- roots: A[:, 0:32] = hi/lo split of clip(causes, -5, 5) ----
    {
        int m = tid >> 2, q = tid & 3;          // 64 rows x 4 col-quads
        const float4* c4 = (const float4*)(causes + (size_t)(row0 + m) * NC + q * 8);
        float4 a = c4[0], b = c4[1];
        float v[8] = { a.x,a.y,a.z,a.w, b.x,b.y,b.z,b.w };
        uint32_t whi[4], wlo[4];
        #pragma unroll
        for (int i = 0; i < 4; ++i) {
            uint16_t h0, l0, h1, l1;
            float v0 = fminf(fmaxf(v[2*i],   -5.f), 5.f);
            float v1 = fminf(fmaxf(v[2*i+1], -5.f), 5.f);
            split16(v0, h0, l0); split16(v1, h1, l1);
            whi[i] = (uint32_t)h0 | ((uint32_t)h1 << 16);
            wlo[i] = (uint32_t)l0 | ((uint32_t)l1 << 16);
        }
        uint32_t base = (uint32_t)m * (AS * 2) + (uint32_t)q * 16;
        *(uint4*)(Ahi + base) = make_uint4(whi[0], whi[1], whi[2], whi[3]);
        *(uint4*)(Alo + base) = make_uint4(wlo[0], wlo[1], wlo[2], wlo[3]);
    }

    // ---- pack B(0) directly ----
    {
        char* bHi = smem + OFF_BP;
        char* bLo = bHi + BHALF;
        for (int e = tid; e < NC * 16; e += NTHREADS) {
            int p = e >> 4, n = e & 15;
            uint16_t h, l; split16(W[(size_t)p * NN + NC + n], h, l);
            uint32_t byte = bOff(p, n);
            *(uint16_t*)(bHi + byte) = h;
            *(uint16_t*)(bLo + byte) = l;
        }
    }
    __syncthreads();

    const uint32_t a_addr = sb + OFF_AHI
                          + (uint32_t)(R + (lane & 15)) * (AS * 2)
                          + (uint32_t)((lane >> 4) * 8) * 2;
    const int bcol = nh * 8 + g;
    const uint32_t bwoff = (uint32_t)(tig * BROW + bcol * 2) * 4;

    for (int k = 0; k < NL; ++k) {
        const int nb   = NC + k * LW;
        const int nch  = nb >> 4;
        const char* bp = smem + OFF_BP + (k & 1) * BBUF;

        // W(k+1) prefetch into registers (static chunk->thread identity map; no smem race)
        float4 wreg[4];
        const int nchunksN = (k < NL - 1) ? (nb + LW) * 4 : 0;
        #pragma unroll
        for (int c2 = 0; c2 < 4; ++c2) {
            int c = tid + c2 * NTHREADS;
            if (c < nchunksN)
                wreg[c2] = *(const float4*)(W + (size_t)(c >> 2) * NN + (nb + LW) + (c & 3) * 4);
        }

        // eps LDG early (consumed in epilogue)
        const int col0 = nb + nh * 8 + 2 * tig;
        float2 ev0 = *(const float2*)(eps + (size_t)(row0 + R + g)     * NN + col0);
        float2 ev1 = *(const float2*)(eps + (size_t)(row0 + R + g + 8) * NN + col0);

        // --- software-pipelined MMA loop (2-slot frag double buffer) ---
        float chh[4] = {0,0,0,0}, chl[4] = {0,0,0,0}, clh[4] = {0,0,0,0};
        Frag F0, F1;
        load_frag(F0, a_addr, bp, bwoff, 0);
        int j = 0;
        for (; j + 2 <= nch; j += 2) {
            load_frag(F1, a_addr, bp, bwoff, j + 1);
            do_mmas(chh, chl, clh, F0);
            if (j + 2 < nch) load_frag(F0, a_addr, bp, bwoff, j + 2);
            do_mmas(chh, chl, clh, F1);
        }
        if (j < nch) do_mmas(chh, chl, clh, F0);   // odd tail (F0 = frag(nch-1))

        // convert register-held W(k+1) -> packed B((k+1)&1)
        if (k < NL - 1) {
            char* bHi = smem + OFF_BP + ((k + 1) & 1) * BBUF;
            char* bLo = bHi + BHALF;
            #pragma unroll
            for (int c2 = 0; c2 < 4; ++c2) {
                int c = tid + c2 * NTHREADS;
                if (c < nchunksN) {
                    int p = c >> 2, s = c & 3;
                    float vv[4] = { wreg[c2].x, wreg[c2].y, wreg[c2].z, wreg[c2].w };
                    #pragma unroll
                    for (int i = 0; i < 4; ++i) {
                        uint16_t h, l; split16(vv[i], h, l);
                        uint32_t byte = bOff(p, s * 4 + i);
                        *(uint16_t*)(bHi + byte) = h;
                        *(uint16_t*)(bLo + byte) = l;
                    }
                }
            }
        }

        // epilogue: z = C + eps, activation, hi/lo split, store back to A
        {
            const int aid0 = acts[col0], aid1 = acts[col0 + 1];
            float z0 = chh[0] + (chl[0] + clh[0]) + ev0.x;
            float z1 = chh[1] + (chl[1] + clh[1]) + ev0.y;
            float z2 = chh[2] + (chl[2] + clh[2]) + ev1.x;
            float z3 = chh[3] + (chl[3] + clh[3]) + ev1.y;
            float a0 = actf(aid0, z0), a1 = actf(aid1, z1);
            float a2 = actf(aid0, z2), a3 = actf(aid1, z3);
            uint16_t h0,l0,h1,l1,h2,l2,h3,l3;
            split16(a0,h0,l0); split16(a1,h1,l1); split16(a2,h2,l2); split16(a3,h3,l3);
            uint32_t b0 = (uint32_t)(R + g)     * (AS * 2) + (uint32_t)col0 * 2;
            uint32_t b1 = (uint32_t)(R + g + 8) * (AS * 2) + (uint32_t)col0 * 2;
            *(uint32_t*)(Ahi + b0) = (uint32_t)h0 | ((uint32_t)h1 << 16);
            *(uint32_t*)(Alo + b0) = (uint32_t)l0 | ((uint32_t)l1 << 16);
            *(uint32_t*)(Ahi + b1) = (uint32_t)h2 | ((uint32_t)h3 << 16);
            *(uint32_t*)(Alo + b1) = (uint32_t)l2 | ((uint32_t)l3 << 16);
        }
        __syncthreads();   // publish A cols + B(k+1)
    }

    // ---- outputs ----
    const int yidx = y_idx_p ? *y_idx_p : (NN - 1);
    float* Xout = out;
    float* yout = out + (size_t)SEQ_LEN * NF;

    if (tid < ROWS) {
        float v = readA(Ahi, Alo, tid, yidx);
        if (v != v) v = 0.f;
        yout[row0 + tid] = v;
    }
    for (int idx = tid; idx < ROWS * NF; idx += NTHREADS) {
        int r = idx / NF, j2 = idx - r * NF;
        float v = readA(Ahi, Alo, r, xs[j2]);
        if (v != v) v = 0.f;
        v = fminf(fmaxf(v, -15.f), 15.f);
        Xout[(size_t)(row0 + r) * NF + j2] = v;
    }
}

extern "C" void kernel_launch(void* const* d_in, const int* in_sizes, int n_in,
                              void* d_out, int out_size)
{
    const float* causes  = (const float*)d_in[0];
    const float* W       = (const float*)d_in[1];
    const float* eps     = (const float*)d_in[2];
    const int*   act_ids = (const int*)d_in[3];
    const int*   x_idx   = (const int*)d_in[4];
    const int*   y_idx_p = (n_in > 5) ? (const int*)d_in[5] : nullptr;
    float*       out     = (float*)d_out;

    cudaFuncSetAttribute(scm_kernel, cudaFuncAttributeMaxDynamicSharedMemorySize, SMEM_BYTES);

    scm_kernel<<<SEQ_LEN / ROWS, NTHREADS, SMEM_BYTES>>>(
        causes, W, eps, act_ids, x_idx, y_idx_p, out);
    (void)in_sizes; (void)out_size;
}